// round 1
// baseline (speedup 1.0000x reference)
#include <cuda_runtime.h>

// ---------------------------------------------------------------------------
// 6-qubit, 3-layer parameterized circuit, B=131072.
// One thread = one quantum state (64 complex amplitudes in registers).
// Qubit q maps to bit (5-q) of the flat amplitude index (C-order of (2,)*6).
// ---------------------------------------------------------------------------

__device__ float g_coef[108];  // per (l,q,j): cos(theta/2), sin(theta/2)

__global__ void prep_kernel(const float* __restrict__ theta) {
    int t = threadIdx.x;
    if (t < 54) {
        float s, c;
        __sincosf(theta[t] * 0.5f, &s, &c);
        g_coef[t * 2 + 0] = c;
        g_coef[t * 2 + 1] = s;
    }
}

// RX(theta): [[c, -i s], [-i s, c]] on qubit Q
template <int Q>
__device__ __forceinline__ void rx_g(float* sr, float* si, float c, float s) {
    constexpr int M = 1 << (5 - Q);
#pragma unroll
    for (int g = 0; g < 32; g++) {
        int i0 = (g & (M - 1)) | ((g & ~(M - 1)) << 1);
        int i1 = i0 | M;
        float ar = sr[i0], ai = si[i0], br = sr[i1], bi = si[i1];
        sr[i0] = c * ar + s * bi;
        si[i0] = c * ai - s * br;
        sr[i1] = c * br + s * ai;
        si[i1] = c * bi - s * ar;
    }
}

// RY(theta): [[c, -s], [s, c]] (real) on qubit Q
template <int Q>
__device__ __forceinline__ void ry_g(float* sr, float* si, float c, float s) {
    constexpr int M = 1 << (5 - Q);
#pragma unroll
    for (int g = 0; g < 32; g++) {
        int i0 = (g & (M - 1)) | ((g & ~(M - 1)) << 1);
        int i1 = i0 | M;
        float ar = sr[i0], ai = si[i0], br = sr[i1], bi = si[i1];
        sr[i0] = c * ar - s * br;
        si[i0] = c * ai - s * bi;
        sr[i1] = s * ar + c * br;
        si[i1] = s * ai + c * bi;
    }
}

// RZ(theta): diag(e^{-i t/2}, e^{+i t/2}); c=cos(t/2), s=sin(t/2)
template <int Q>
__device__ __forceinline__ void rz_g(float* sr, float* si, float c, float s) {
    constexpr int M = 1 << (5 - Q);
#pragma unroll
    for (int i = 0; i < 64; i++) {
        float r = sr[i], m = si[i];
        if (i & M) {  // * (c, +s)
            sr[i] = c * r - s * m;
            si[i] = c * m + s * r;
        } else {      // * (c, -s)
            sr[i] = c * r + s * m;
            si[i] = c * m - s * r;
        }
    }
}

// CNOT(control C, target T): pure permutation -> free after full unroll
template <int C, int T>
__device__ __forceinline__ void cnot_g(float* sr, float* si) {
    constexpr int MC = 1 << (5 - C);
    constexpr int MT = 1 << (5 - T);
#pragma unroll
    for (int i = 0; i < 64; i++) {
        if ((i & MC) && !(i & MT)) {
            int j = i | MT;
            float tr = sr[i]; sr[i] = sr[j]; sr[j] = tr;
            float ti = si[i]; si[i] = si[j]; si[j] = ti;
        }
    }
}

__global__ __launch_bounds__(128, 1) void qsim_kernel(
    const float* __restrict__ x, float* __restrict__ out, int Bn)
{
    int b = blockIdx.x * blockDim.x + threadIdx.x;
    if (b >= Bn) return;

    // --- encoding angles: mean of each 4-feature chunk, clip, scale ---
    // u_q = per-qubit 2-vector after RX(a) RZ(a/2) on |0>:
    //   u0 = ( c2*c4, -c2*s4 ),  u1 = ( s2*s4, -s2*c4 )
    const float4* x4 = reinterpret_cast<const float4*>(x) + (long)b * 6;
    float u0r[6], u0i[6], u1r[6], u1i[6];
#pragma unroll
    for (int q = 0; q < 6; q++) {
        float4 v = __ldg(&x4[q]);
        float a = (v.x + v.y + v.z + v.w) * 0.25f;
        a = fminf(6.0f, fmaxf(-6.0f, a)) * (3.14159265358979323846f / 6.0f);
        float s2, c2, s4, c4;
        __sincosf(a * 0.5f, &s2, &c2);
        __sincosf(a * 0.25f, &s4, &c4);
        u0r[q] = c2 * c4;  u0i[q] = -c2 * s4;
        u1r[q] = s2 * s4;  u1i[q] = -s2 * c4;
    }

    // --- build product state (tensor product, LSB qubit 5 first) ---
    float sr[64], si[64];
    sr[0] = 1.0f; si[0] = 0.0f;
#pragma unroll
    for (int qq = 0; qq < 6; qq++) {
        int q = 5 - qq;
        int n = 1 << qq;
#pragma unroll
        for (int j = 0; j < 64; j++) {
            if (j < n) {  // constant-folds under full unroll
                float tr = sr[j], ti = si[j];
                sr[j + n] = tr * u1r[q] - ti * u1i[q];
                si[j + n] = tr * u1i[q] + ti * u1r[q];
                sr[j]     = tr * u0r[q] - ti * u0i[q];
                si[j]     = tr * u0i[q] + ti * u0r[q];
            }
        }
    }

    // --- entangling layers ---
#pragma unroll
    for (int l = 0; l < 3; l++) {
        cnot_g<0, 1>(sr, si);
        cnot_g<1, 2>(sr, si);
        cnot_g<2, 3>(sr, si);
        cnot_g<3, 4>(sr, si);
        cnot_g<4, 5>(sr, si);
        cnot_g<5, 0>(sr, si);
        const float* cf = g_coef + l * 36;
#define GQ(Q)                                              \
        rx_g<Q>(sr, si, cf[Q * 6 + 0], cf[Q * 6 + 1]);     \
        ry_g<Q>(sr, si, cf[Q * 6 + 2], cf[Q * 6 + 3]);     \
        rz_g<Q>(sr, si, cf[Q * 6 + 4], cf[Q * 6 + 5]);
        GQ(0) GQ(1) GQ(2) GQ(3) GQ(4) GQ(5)
#undef GQ
    }

    // --- measurements ---
    // Z on q: +p if bit(5-q)==0 else -p.  Masks: q0->32, q2->8, q4->2
    float z0 = 0.0f, z2 = 0.0f, z4 = 0.0f;
#pragma unroll
    for (int i = 0; i < 64; i++) {
        float p = sr[i] * sr[i] + si[i] * si[i];
        z0 = (i & 32) ? z0 - p : z0 + p;
        z2 = (i & 8)  ? z2 - p : z2 + p;
        z4 = (i & 2)  ? z4 - p : z4 + p;
    }
    // X on q: 2 * sum_{i: bit=0} (re_i re_j + im_i im_j), j = i ^ mask
    // Masks: q1->16, q3->4, q5->1
    float x1 = 0.0f, x3 = 0.0f, x5 = 0.0f;
#pragma unroll
    for (int i = 0; i < 64; i++) {
        if (!(i & 16)) { int j = i | 16; x1 += sr[i] * sr[j] + si[i] * si[j]; }
        if (!(i & 4))  { int j = i | 4;  x3 += sr[i] * sr[j] + si[i] * si[j]; }
        if (!(i & 1))  { int j = i | 1;  x5 += sr[i] * sr[j] + si[i] * si[j]; }
    }
    x1 *= 2.0f; x3 *= 2.0f; x5 *= 2.0f;

    // out row: [Z0, X1, Z2, X3, Z4, X5, Z0, X1]
    float4* o4 = reinterpret_cast<float4*>(out) + (long)b * 2;
    o4[0] = make_float4(z0, x1, z2, x3);
    o4[1] = make_float4(z4, x5, z0, x1);
}

extern "C" void kernel_launch(void* const* d_in, const int* in_sizes, int n_in,
                              void* d_out, int out_size) {
    const float* x     = (const float*)d_in[0];
    const float* theta = (const float*)d_in[1];
    float* out = (float*)d_out;
    int Bn = in_sizes[0] / 24;

    prep_kernel<<<1, 64>>>(theta);
    int blocks = (Bn + 127) / 128;
    qsim_kernel<<<blocks, 128>>>(x, out, Bn);
}

// round 2
// speedup vs baseline: 1.6481x; 1.6481x over previous
#include <cuda_runtime.h>

// ---------------------------------------------------------------------------
// 6-qubit, 3-layer parameterized circuit, B=131072, f32x2-packed simulation.
// One thread = one state. State stored SoA as 32 packed-real + 32 packed-imag
// f32x2 registers; pack p holds amplitudes (2p, 2p+1)  [pair dim = qubit 5].
// Qubit q maps to bit (5-q) of the flat amplitude index.
// ---------------------------------------------------------------------------

typedef unsigned long long u64;
#define SGN2 0x8000000080000000ULL

__device__ __forceinline__ u64 pk2(float a, float b) {
    u64 r; asm("mov.b64 %0,{%1,%2};" : "=l"(r) : "f"(a), "f"(b)); return r;
}
__device__ __forceinline__ void upk2(u64 v, float& a, float& b) {
    asm("mov.b64 {%0,%1},%2;" : "=f"(a), "=f"(b) : "l"(v));
}
__device__ __forceinline__ u64 bc2(float a) { return pk2(a, a); }
__device__ __forceinline__ u64 f2mul(u64 a, u64 b) {
    u64 d; asm("mul.rn.f32x2 %0,%1,%2;" : "=l"(d) : "l"(a), "l"(b)); return d;
}
__device__ __forceinline__ u64 f2fma(u64 a, u64 b, u64 c) {
    u64 d; asm("fma.rn.f32x2 %0,%1,%2,%3;" : "=l"(d) : "l"(a), "l"(b), "l"(c)); return d;
}
__device__ __forceinline__ u64 f2add(u64 a, u64 b) {
    u64 d; asm("add.rn.f32x2 %0,%1,%2;" : "=l"(d) : "l"(a), "l"(b)); return d;
}
__device__ __forceinline__ u64 f2swap(u64 a) {
    u64 d;
    asm("{\n\t.reg .b32 x,y;\n\tmov.b64 {x,y},%1;\n\tmov.b64 %0,{y,x};\n\t}"
        : "=l"(d) : "l"(a));
    return d;
}

// per gate t=(l*18+q*3+j): [cc=(c,c), ss=(s,s), ns=(-s,-s), sm=(-s,s)]
__device__ u64 g_cf[54 * 4];

__global__ void prep_kernel(const float* __restrict__ theta) {
    int t = threadIdx.x;
    if (t < 54) {
        float s, c;
        __sincosf(theta[t] * 0.5f, &s, &c);
        g_cf[t * 4 + 0] = pk2(c, c);
        g_cf[t * 4 + 1] = pk2(s, s);
        g_cf[t * 4 + 2] = pk2(-s, -s);
        g_cf[t * 4 + 3] = pk2(-s, s);
    }
}

// ---- gates on qubits 0..4 (pack-aligned butterflies) ----
template <int Q>
__device__ __forceinline__ void rx_p(u64* R, u64* I, u64 cc, u64 ss, u64 ns) {
    constexpr int Mp = 1 << (4 - Q);
#pragma unroll
    for (int g = 0; g < 16; g++) {
        int p0 = (g & (Mp - 1)) | ((g & ~(Mp - 1)) << 1);
        int p1 = p0 | Mp;
        u64 Ar = R[p0], Ai = I[p0], Br = R[p1], Bi = I[p1];
        R[p0] = f2fma(ss, Bi, f2mul(cc, Ar));
        I[p0] = f2fma(ns, Br, f2mul(cc, Ai));
        R[p1] = f2fma(ss, Ai, f2mul(cc, Br));
        I[p1] = f2fma(ns, Ar, f2mul(cc, Bi));
    }
}

template <int Q>
__device__ __forceinline__ void ry_p(u64* R, u64* I, u64 cc, u64 ss, u64 ns) {
    constexpr int Mp = 1 << (4 - Q);
#pragma unroll
    for (int g = 0; g < 16; g++) {
        int p0 = (g & (Mp - 1)) | ((g & ~(Mp - 1)) << 1);
        int p1 = p0 | Mp;
        u64 Ar = R[p0], Ai = I[p0], Br = R[p1], Bi = I[p1];
        R[p0] = f2fma(ns, Br, f2mul(cc, Ar));
        I[p0] = f2fma(ns, Bi, f2mul(cc, Ai));
        R[p1] = f2fma(ss, Ar, f2mul(cc, Br));
        I[p1] = f2fma(ss, Ai, f2mul(cc, Bi));
    }
}

template <int Q>
__device__ __forceinline__ void rz_p(u64* R, u64* I, u64 cc, u64 ss, u64 ns) {
    constexpr int M = 1 << (5 - Q);  // >= 2
#pragma unroll
    for (int p = 0; p < 32; p++) {
        u64 r = R[p], m = I[p];
        if ((2 * p) & M) {
            R[p] = f2fma(ns, m, f2mul(cc, r));
            I[p] = f2fma(ss, r, f2mul(cc, m));
        } else {
            R[p] = f2fma(ss, m, f2mul(cc, r));
            I[p] = f2fma(ns, r, f2mul(cc, m));
        }
    }
}

// ---- gates on qubit 5 (within-pack butterflies via half-swap) ----
__device__ __forceinline__ void rx5_p(u64* R, u64* I, u64 cc, u64 ss, u64 ns) {
#pragma unroll
    for (int p = 0; p < 32; p++) {
        u64 r = R[p], m = I[p];
        R[p] = f2fma(ss, f2swap(m), f2mul(cc, r));
        I[p] = f2fma(ns, f2swap(r), f2mul(cc, m));
    }
}
__device__ __forceinline__ void ry5_p(u64* R, u64* I, u64 cc, u64 sm) {  // sm=(-s,s)
#pragma unroll
    for (int p = 0; p < 32; p++) {
        u64 r = R[p], m = I[p];
        R[p] = f2fma(sm, f2swap(r), f2mul(cc, r));
        I[p] = f2fma(sm, f2swap(m), f2mul(cc, m));
    }
}
__device__ __forceinline__ void rz5_p(u64* R, u64* I, u64 cc, u64 zs, u64 zm) {
    // zs=(s,-s), zm=(-s,s)
#pragma unroll
    for (int p = 0; p < 32; p++) {
        u64 r = R[p], m = I[p];
        R[p] = f2fma(zs, m, f2mul(cc, r));
        I[p] = f2fma(zm, r, f2mul(cc, m));
    }
}

// ---- CNOTs ----
template <int C, int T>  // C,T in 0..4 -> pure pack permutation (free)
__device__ __forceinline__ void cnot_p(u64* R, u64* I) {
    constexpr int MC = 1 << (5 - C), MTp = 1 << (4 - T);
#pragma unroll
    for (int p = 0; p < 32; p++) {
        if (((2 * p) & MC) && !(p & MTp)) {
            int q = p | MTp;
            u64 t = R[p]; R[p] = R[q]; R[q] = t;
            t = I[p]; I[p] = I[q]; I[q] = t;
        }
    }
}
__device__ __forceinline__ void cnot45_p(u64* R, u64* I) {  // control q4, target q5
#pragma unroll
    for (int p = 1; p < 32; p += 2) {
        R[p] = f2swap(R[p]);
        I[p] = f2swap(I[p]);
    }
}
__device__ __forceinline__ void cnot50_p(u64* R, u64* I) {  // control q5, target q0
#pragma unroll
    for (int p = 0; p < 16; p++) {
        float a0, a1, b0, b1;
        upk2(R[p], a0, a1); upk2(R[p + 16], b0, b1);
        R[p] = pk2(a0, b1); R[p + 16] = pk2(b0, a1);
        upk2(I[p], a0, a1); upk2(I[p + 16], b0, b1);
        I[p] = pk2(a0, b1); I[p + 16] = pk2(b0, a1);
    }
}

__global__ __launch_bounds__(128, 3) void qsim_kernel(
    const float* __restrict__ x, float* __restrict__ out, int Bn)
{
    int b = blockIdx.x * blockDim.x + threadIdx.x;
    if (b >= Bn) return;

    // --- encoding: per-qubit 2-vector after RX(a) RZ(a/2) on |0> ---
    const float4* x4 = reinterpret_cast<const float4*>(x) + (long)b * 6;
    float u0r[6], u0i[6], u1r[6], u1i[6];
#pragma unroll
    for (int q = 0; q < 6; q++) {
        float4 v = __ldg(&x4[q]);
        float a = (v.x + v.y + v.z + v.w) * 0.25f;
        a = fminf(6.0f, fmaxf(-6.0f, a)) * (3.14159265358979323846f / 6.0f);
        float s2, c2, s4, c4;
        __sincosf(a * 0.5f, &s2, &c2);
        __sincosf(a * 0.25f, &s4, &c4);
        u0r[q] = c2 * c4;  u0i[q] = -c2 * s4;
        u1r[q] = s2 * s4;  u1i[q] = -s2 * c4;
    }

    // --- product state, packed: pack dim = qubit 5 first ---
    u64 R[32], I[32];
    R[0] = pk2(u0r[5], u1r[5]);
    I[0] = pk2(u0i[5], u1i[5]);
#pragma unroll
    for (int qq = 1; qq < 6; qq++) {
        int q = 5 - qq;
        int n2 = 1 << (qq - 1);
        u64 a0 = bc2(u0r[q]), b0 = bc2(u0i[q]), nb0 = bc2(-u0i[q]);
        u64 a1 = bc2(u1r[q]), b1 = bc2(u1i[q]), nb1 = bc2(-u1i[q]);
#pragma unroll
        for (int j = 0; j < 16; j++) {
            if (j < n2) {  // constant-folds under full unroll
                u64 tr = R[j], ti = I[j];
                R[j + n2] = f2fma(nb1, ti, f2mul(a1, tr));
                I[j + n2] = f2fma(b1, tr, f2mul(a1, ti));
                R[j]      = f2fma(nb0, ti, f2mul(a0, tr));
                I[j]      = f2fma(b0, tr, f2mul(a0, ti));
            }
        }
    }

    // --- entangling layers ---
#pragma unroll
    for (int l = 0; l < 3; l++) {
        cnot_p<0, 1>(R, I);
        cnot_p<1, 2>(R, I);
        cnot_p<2, 3>(R, I);
        cnot_p<3, 4>(R, I);
        cnot45_p(R, I);
        cnot50_p(R, I);
        const u64* cf = g_cf + l * 72;  // 18 gates * 4 entries
#define GOFF(q, j) ((q) * 12 + (j) * 4)
#define GQ(Q)                                                              \
        rx_p<Q>(R, I, cf[GOFF(Q,0)+0], cf[GOFF(Q,0)+1], cf[GOFF(Q,0)+2]);  \
        ry_p<Q>(R, I, cf[GOFF(Q,1)+0], cf[GOFF(Q,1)+1], cf[GOFF(Q,1)+2]);  \
        rz_p<Q>(R, I, cf[GOFF(Q,2)+0], cf[GOFF(Q,2)+1], cf[GOFF(Q,2)+2]);
        GQ(0) GQ(1) GQ(2) GQ(3) GQ(4)
#undef GQ
        // qubit 5 gates
        rx5_p(R, I, cf[GOFF(5,0)+0], cf[GOFF(5,0)+1], cf[GOFF(5,0)+2]);
        ry5_p(R, I, cf[GOFF(5,1)+0], cf[GOFF(5,1)+3]);
        {
            u64 zm = cf[GOFF(5,2)+3];     // (-s, s)
            u64 zs = zm ^ SGN2;           // ( s,-s)
            rz5_p(R, I, cf[GOFF(5,2)+0], zs, zm);
        }
#undef GOFF
    }

    // --- measurements (packed accumulation) ---
    u64 az0 = 0, az2 = 0, az4 = 0;           // +0.0f pairs
    u64 ax1 = 0, ax3 = 0, ax5 = 0;
#pragma unroll
    for (int p = 0; p < 32; p++) {
        u64 pr = f2fma(I[p], I[p], f2mul(R[p], R[p]));
        az0 = f2add(az0, ((2 * p) & 32) ? (pr ^ SGN2) : pr);
        az2 = f2add(az2, ((2 * p) & 8)  ? (pr ^ SGN2) : pr);
        az4 = f2add(az4, ((2 * p) & 2)  ? (pr ^ SGN2) : pr);
        if (!(p & 8)) ax1 = f2fma(R[p], R[p | 8], f2fma(I[p], I[p | 8], ax1));
        if (!(p & 2)) ax3 = f2fma(R[p], R[p | 2], f2fma(I[p], I[p | 2], ax3));
        ax5 = f2fma(R[p], f2swap(R[p]), f2fma(I[p], f2swap(I[p]), ax5));
    }
    float lo, hi;
    upk2(az0, lo, hi); float z0 = lo + hi;
    upk2(az2, lo, hi); float z2 = lo + hi;
    upk2(az4, lo, hi); float z4 = lo + hi;
    upk2(ax1, lo, hi); float x1 = 2.0f * (lo + hi);
    upk2(ax3, lo, hi); float x3 = 2.0f * (lo + hi);
    upk2(ax5, lo, hi); float x5 = 2.0f * lo;  // both halves hold the same sum

    // out row: [Z0, X1, Z2, X3, Z4, X5, Z0, X1]
    float4* o4 = reinterpret_cast<float4*>(out) + (long)b * 2;
    o4[0] = make_float4(z0, x1, z2, x3);
    o4[1] = make_float4(z4, x5, z0, x1);
}

extern "C" void kernel_launch(void* const* d_in, const int* in_sizes, int n_in,
                              void* d_out, int out_size) {
    const float* x     = (const float*)d_in[0];
    const float* theta = (const float*)d_in[1];
    float* out = (float*)d_out;
    int Bn = in_sizes[0] / 24;

    prep_kernel<<<1, 64>>>(theta);
    int blocks = (Bn + 127) / 128;
    qsim_kernel<<<blocks, 128>>>(x, out, Bn);
}